// round 7
// baseline (speedup 1.0000x reference)
#include <cuda_runtime.h>
#include <cstdint>

#define BH 16
#define NS 256
#define DH 64
#define EPSF 1.1920929e-07f

// ---------------- scratch (device globals; no allocs) ----------------
__device__ __align__(16) float g_qkv[512 * 2560];
__device__ __align__(16) float g_qn [BH * NS * DH];
__device__ __align__(16) float g_k1 [BH * NS * DH];
__device__ __align__(16) float g_k2 [BH * NS * DH];
__device__ __align__(16) float g_v1t[BH * DH * NS];
__device__ __align__(16) float g_v2t[BH * DH * NS];
__device__ __align__(16) float g_e1 [BH * NS * NS];
__device__ __align__(16) float g_e2 [BH * NS * NS];
__device__ __align__(16) float g_e3 [BH * NS * NS];
__device__ __align__(16) float g_num[BH * NS * DH];
__device__ __align__(16) float g_den[BH * NS];
__device__ __align__(16) float g_o  [512 * 512];

// ---------------- generic SGEMM: C[M,N] = A[M,K] @ B[K,N] ----------------
// 128x64 block tile, 256 threads, 8x4 micro, k-tile 16. All dims multiples.
__global__ void sgemm128x64(const float* __restrict__ A, const float* __restrict__ B,
                            float* __restrict__ C, int M, int N, int K) {
    __shared__ float As[16][128];
    __shared__ float Bs[16][64];
    int t = threadIdx.x;
    int tx = t & 15, ty = t >> 4;
    int m0 = blockIdx.y * 128, n0 = blockIdx.x * 64;

    float acc[8][4];
#pragma unroll
    for (int i = 0; i < 8; i++)
#pragma unroll
        for (int j = 0; j < 4; j++) acc[i][j] = 0.f;

    for (int kt = 0; kt < K; kt += 16) {
#pragma unroll
        for (int q = 0; q < 2; q++) {
            int lin = t + q * 256;           // 0..511
            int m = lin & 127, kq = lin >> 7; // kq 0..3
            float4 v = *(const float4*)&A[(size_t)(m0 + m) * K + kt + kq * 4];
            As[kq * 4 + 0][m] = v.x; As[kq * 4 + 1][m] = v.y;
            As[kq * 4 + 2][m] = v.z; As[kq * 4 + 3][m] = v.w;
        }
        {
            int kk = t >> 4, nq = t & 15;
            float4 v = *(const float4*)&B[(size_t)(kt + kk) * N + n0 + nq * 4];
            *(float4*)&Bs[kk][nq * 4] = v;
        }
        __syncthreads();
#pragma unroll
        for (int kk = 0; kk < 16; kk++) {
            float4 b = *(float4*)&Bs[kk][tx * 4];
            float a[8];
#pragma unroll
            for (int i = 0; i < 8; i++) a[i] = As[kk][ty * 8 + i];
#pragma unroll
            for (int i = 0; i < 8; i++) {
                acc[i][0] += a[i] * b.x; acc[i][1] += a[i] * b.y;
                acc[i][2] += a[i] * b.z; acc[i][3] += a[i] * b.w;
            }
        }
        __syncthreads();
    }
#pragma unroll
    for (int i = 0; i < 8; i++) {
        float4 v = make_float4(acc[i][0], acc[i][1], acc[i][2], acc[i][3]);
        *(float4*)&C[(size_t)(m0 + ty * 8 + i) * N + n0 + tx * 4] = v;
    }
}

// ---------------- split + rmsnorm + pack ----------------
// one block (64 threads) per (bh, n)
__global__ void pack_norm(const float* __restrict__ qw,
                          const float* __restrict__ k1w,
                          const float* __restrict__ k2w) {
    int blk = blockIdx.x;            // 0..4095
    int bh = blk >> 8, n = blk & 255;
    int b = bh >> 3, h = bh & 7;
    int dd = threadIdx.x;            // 0..63
    size_t base = (size_t)(b * 256 + n) * 2560 + h * 64 + dd;
    float q  = g_qkv[base];
    float k1 = g_qkv[base + 512];
    float k2 = g_qkv[base + 1024];
    float v1 = g_qkv[base + 1536];
    float v2 = g_qkv[base + 2048];

    __shared__ float sw[3][2];
    float sq = q * q, s1 = k1 * k1, s2 = k2 * k2;
#pragma unroll
    for (int o = 16; o; o >>= 1) {
        sq += __shfl_xor_sync(0xffffffffu, sq, o);
        s1 += __shfl_xor_sync(0xffffffffu, s1, o);
        s2 += __shfl_xor_sync(0xffffffffu, s2, o);
    }
    int w = dd >> 5;
    if ((dd & 31) == 0) { sw[0][w] = sq; sw[1][w] = s1; sw[2][w] = s2; }
    __syncthreads();
    float rq = rsqrtf((sw[0][0] + sw[0][1]) * (1.f / 64.f) + EPSF);
    float r1 = rsqrtf((sw[1][0] + sw[1][1]) * (1.f / 64.f) + EPSF);
    float r2 = rsqrtf((sw[2][0] + sw[2][1]) * (1.f / 64.f) + EPSF);

    int rb = bh * NS * DH + n * DH + dd;
    g_qn[rb] = q * rq * qw[dd] * 0.125f;   // fold q*scale
    g_k1[rb] = k1 * r1 * k1w[dd];
    g_k2[rb] = k2 * r2 * k2w[dd];
    g_v1t[bh * DH * NS + dd * NS + n] = v1;
    g_v2t[bh * DH * NS + dd * NS + n] = v2;
}

// ---------------- sims: e = exp(clip(scale * L @ R^T)) ----------------
// C[m][n] = exp(clip(scale * sum_d L[m,d]*R[n,d])), L,R: [256,64] row-major.
// block: 128m x 64n, 256 threads, 8x4 micro, K=64.
__global__ void sims_kernel() {
    int z = blockIdx.z;
    int bh = z / 3, mat = z % 3;
    const float* L = ((mat == 2) ? g_k1 : g_qn) + bh * NS * DH;
    const float* R = ((mat == 0) ? g_k1 : g_k2) + bh * NS * DH;
    float* C = ((mat == 0) ? g_e1 : (mat == 1) ? g_e2 : g_e3) + (size_t)bh * NS * NS;
    float scale = (mat == 2) ? 0.125f : 1.f;

    __shared__ float As[16][128];
    __shared__ float Bs[16][64];
    int t = threadIdx.x, tx = t & 15, ty = t >> 4;
    int m0 = blockIdx.y * 128, n0 = blockIdx.x * 64;

    float acc[8][4];
#pragma unroll
    for (int i = 0; i < 8; i++)
#pragma unroll
        for (int j = 0; j < 4; j++) acc[i][j] = 0.f;

    for (int kt = 0; kt < 64; kt += 16) {
#pragma unroll
        for (int q = 0; q < 2; q++) {
            int lin = t + q * 256;
            int m = lin & 127, kq = lin >> 7;
            float4 v = *(const float4*)&L[(m0 + m) * 64 + kt + kq * 4];
            As[kq * 4 + 0][m] = v.x; As[kq * 4 + 1][m] = v.y;
            As[kq * 4 + 2][m] = v.z; As[kq * 4 + 3][m] = v.w;
        }
        {
            int n = t & 63, kq = t >> 6;
            float4 v = *(const float4*)&R[(n0 + n) * 64 + kt + kq * 4];
            Bs[kq * 4 + 0][n] = v.x; Bs[kq * 4 + 1][n] = v.y;
            Bs[kq * 4 + 2][n] = v.z; Bs[kq * 4 + 3][n] = v.w;
        }
        __syncthreads();
#pragma unroll
        for (int kk = 0; kk < 16; kk++) {
            float4 b = *(float4*)&Bs[kk][tx * 4];
            float a[8];
#pragma unroll
            for (int i = 0; i < 8; i++) a[i] = As[kk][ty * 8 + i];
#pragma unroll
            for (int i = 0; i < 8; i++) {
                acc[i][0] += a[i] * b.x; acc[i][1] += a[i] * b.y;
                acc[i][2] += a[i] * b.z; acc[i][3] += a[i] * b.w;
            }
        }
        __syncthreads();
    }
#pragma unroll
    for (int i = 0; i < 8; i++) {
        float4 v;
        v.x = __expf(fminf(40.f, fmaxf(-40.f, acc[i][0] * scale)));
        v.y = __expf(fminf(40.f, fmaxf(-40.f, acc[i][1] * scale)));
        v.z = __expf(fminf(40.f, fmaxf(-40.f, acc[i][2] * scale)));
        v.w = __expf(fminf(40.f, fmaxf(-40.f, acc[i][3] * scale)));
        *(float4*)&C[(size_t)(m0 + ty * 8 + i) * NS + n0 + tx * 4] = v;
    }
}

// ---------------- heavy: per (bh, channel d, 64-row i-block) ----------------
// G[i,j] = sum_k (e2[i,k]*v2[k,d]) * e3[j,k]  (full 64x256 G in registers)
// out[i] = sum_j e1[i,j]*v1[j,d]*G[i,j]  -> g_num (d<64) or g_den (d==64)
__global__ void __launch_bounds__(256, 2) heavy_kernel() {
    int d  = blockIdx.x;     // 0..64 (64 = den channel)
    int ib = blockIdx.y;     // 0..3
    int bh = blockIdx.z;     // 0..15

    __shared__ __align__(16) float As[16][64];
    __shared__ __align__(16) float Bs[16][256];
    __shared__ __align__(16) float vw1[256];
    __shared__ __align__(16) float vw2[256];
    __shared__ float red[64];

    int t = threadIdx.x, tx = t & 15, ty = t >> 4;
    const float* e2 = g_e2 + (size_t)bh * NS * NS + (size_t)ib * 64 * NS;
    const float* e3 = g_e3 + (size_t)bh * NS * NS;
    const float* e1 = g_e1 + (size_t)bh * NS * NS + (size_t)ib * 64 * NS;

    vw2[t] = (d < 64) ? g_v2t[bh * DH * NS + d * NS + t] : 1.f;
    vw1[t] = (d < 64) ? g_v1t[bh * DH * NS + d * NS + t] : 1.f;
    __syncthreads();

    // acc[ii][s*4+c] = G[ty*4+ii][s*64 + tx*4 + c]
    float acc[4][16];
#pragma unroll
    for (int i = 0; i < 4; i++)
#pragma unroll
        for (int j = 0; j < 16; j++) acc[i][j] = 0.f;

    for (int kt = 0; kt < 256; kt += 16) {
        {   // A tile: 64 i x 16 k, scaled by v2
            int i = t >> 2, kq = t & 3;
            float4 v = *(const float4*)&e2[i * NS + kt + kq * 4];
            As[kq * 4 + 0][i] = v.x * vw2[kt + kq * 4 + 0];
            As[kq * 4 + 1][i] = v.y * vw2[kt + kq * 4 + 1];
            As[kq * 4 + 2][i] = v.z * vw2[kt + kq * 4 + 2];
            As[kq * 4 + 3][i] = v.w * vw2[kt + kq * 4 + 3];
        }
#pragma unroll
        for (int q = 0; q < 4; q++) {  // B tile: 256 j x 16 k
            float4 v = *(const float4*)&e3[t * NS + kt + q * 4];
            Bs[q * 4 + 0][t] = v.x; Bs[q * 4 + 1][t] = v.y;
            Bs[q * 4 + 2][t] = v.z; Bs[q * 4 + 3][t] = v.w;
        }
        __syncthreads();
#pragma unroll
        for (int kk = 0; kk < 16; kk++) {
            float4 a = *(float4*)&As[kk][ty * 4];
            float av[4] = {a.x, a.y, a.z, a.w};
#pragma unroll
            for (int s = 0; s < 4; s++) {
                float4 b = *(float4*)&Bs[kk][s * 64 + tx * 4];
#pragma unroll
                for (int ii = 0; ii < 4; ii++) {
                    acc[ii][s * 4 + 0] += av[ii] * b.x;
                    acc[ii][s * 4 + 1] += av[ii] * b.y;
                    acc[ii][s * 4 + 2] += av[ii] * b.z;
                    acc[ii][s * 4 + 3] += av[ii] * b.w;
                }
            }
        }
        __syncthreads();
    }

    // epilogue: sum_j e1[i,j]*v1[j]*G[i,j]; reduce 16 tx lanes per i via shfl
#pragma unroll
    for (int ii = 0; ii < 4; ii++) {
        int i = ty * 4 + ii;
        float sum = 0.f;
#pragma unroll
        for (int s = 0; s < 4; s++) {
            int j = s * 64 + tx * 4;
            float4 ev = *(const float4*)&e1[i * NS + j];
            float4 wv = *(const float4*)&vw1[j];
            sum += ev.x * wv.x * acc[ii][s * 4 + 0];
            sum += ev.y * wv.y * acc[ii][s * 4 + 1];
            sum += ev.z * wv.z * acc[ii][s * 4 + 2];
            sum += ev.w * wv.w * acc[ii][s * 4 + 3];
        }
#pragma unroll
        for (int o = 8; o; o >>= 1) sum += __shfl_xor_sync(0xffffffffu, sum, o);
        if (tx == 0) red[i] = sum;    // one writer per i: deterministic
    }
    __syncthreads();
    if (t < 64) {
        int ig = ib * 64 + t;
        if (d < 64) g_num[bh * NS * DH + ig * DH + d] = red[t];
        else        g_den[bh * NS + ig] = red[t];
    }
}

// ---------------- normalize: o[(b*256+i)][h*64+dd] = num/den ----------------
__global__ void normalize_kernel() {
    int idx = blockIdx.x * 256 + threadIdx.x;   // 0..262143
    int dd = idx & 63;
    int i  = (idx >> 6) & 255;
    int bh = idx >> 14;
    int b = bh >> 3, h = bh & 7;
    float v = g_num[idx] / g_den[bh * NS + i];
    g_o[(size_t)(b * 256 + i) * 512 + h * 64 + dd] = v;
}

extern "C" void kernel_launch(void* const* d_in, const int* in_sizes, int n_in,
                              void* d_out, int out_size) {
    const float* x     = (const float*)d_in[0];
    const float* w_qkv = (const float*)d_in[1];
    const float* w_out = (const float*)d_in[2];
    const float* qw    = (const float*)d_in[3];
    const float* k1w   = (const float*)d_in[4];
    const float* k2w   = (const float*)d_in[5];
    float* out = (float*)d_out;

    float *qkv_p = nullptr, *o_p = nullptr;
    cudaGetSymbolAddress((void**)&qkv_p, g_qkv);
    cudaGetSymbolAddress((void**)&o_p, g_o);

    // 1) qkv = x @ w_qkv   [512,512]@[512,2560]
    sgemm128x64<<<dim3(40, 4), 256>>>(x, w_qkv, qkv_p, 512, 2560, 512);
    // 2) split + rmsnorm + pack
    pack_norm<<<4096, 64>>>(qw, k1w, k2w);
    // 3) e1/e2/e3
    sims_kernel<<<dim3(4, 2, 48), 256>>>();
    // 4) heavy factorized attention (65 channels: 64 num + 1 den)
    heavy_kernel<<<dim3(65, 4, 16), 256>>>();
    // 5) normalize
    normalize_kernel<<<1024, 256>>>();
    // 6) out = o @ w_out   [512,512]@[512,512]
    sgemm128x64<<<dim3(8, 4), 256>>>(o_p, w_out, out, 512, 512, 512);
}

// round 9
// speedup vs baseline: 1.8271x; 1.8271x over previous
#include <cuda_runtime.h>
#include <cstdint>

#define BH 16
#define NS 256
#define DH 64
#define EPSF 1.1920929e-07f

// ---------------- scratch (device globals; no allocs) ----------------
__device__ __align__(16) float g_qkv[512 * 2560];
__device__ __align__(16) float g_qn [BH * NS * DH];
__device__ __align__(16) float g_k1 [BH * NS * DH];
__device__ __align__(16) float g_k2 [BH * NS * DH];
__device__ __align__(16) float g_v1t[BH * DH * NS];
__device__ __align__(16) float g_v2t[BH * DH * NS];
__device__ __align__(16) float g_e1 [BH * NS * NS];
__device__ __align__(16) float g_e2 [BH * NS * NS];
__device__ __align__(16) float g_e3 [BH * NS * NS];
__device__ __align__(16) float g_numP[4][BH * NS * DH];
__device__ __align__(16) float g_denP[4][BH * NS];
__device__ __align__(16) float g_o  [512 * 512];

__device__ __forceinline__ uint32_t cvt_tf32(float x) {
    uint32_t r; asm("cvt.rna.tf32.f32 %0, %1;" : "=r"(r) : "f"(x)); return r;
}

__device__ __forceinline__ void mma_tf32(float* c,
        uint32_t a0, uint32_t a1, uint32_t a2, uint32_t a3,
        uint32_t b0, uint32_t b1) {
    asm volatile("mma.sync.aligned.m16n8k8.row.col.f32.tf32.tf32.f32 "
        "{%0,%1,%2,%3}, {%4,%5,%6,%7}, {%8,%9}, {%0,%1,%2,%3};"
        : "+f"(c[0]), "+f"(c[1]), "+f"(c[2]), "+f"(c[3])
        : "r"(a0), "r"(a1), "r"(a2), "r"(a3), "r"(b0), "r"(b1));
}

// ---------------- generic SGEMM: C[M,N] = A[M,K] @ B[K,N] ----------------
__global__ void sgemm128x64(const float* __restrict__ A, const float* __restrict__ B,
                            float* __restrict__ C, int M, int N, int K) {
    __shared__ float As[16][128];
    __shared__ float Bs[16][64];
    int t = threadIdx.x;
    int tx = t & 15, ty = t >> 4;
    int m0 = blockIdx.y * 128, n0 = blockIdx.x * 64;

    float acc[8][4];
#pragma unroll
    for (int i = 0; i < 8; i++)
#pragma unroll
        for (int j = 0; j < 4; j++) acc[i][j] = 0.f;

    for (int kt = 0; kt < K; kt += 16) {
#pragma unroll
        for (int q = 0; q < 2; q++) {
            int lin = t + q * 256;
            int m = lin & 127, kq = lin >> 7;
            float4 v = *(const float4*)&A[(size_t)(m0 + m) * K + kt + kq * 4];
            As[kq * 4 + 0][m] = v.x; As[kq * 4 + 1][m] = v.y;
            As[kq * 4 + 2][m] = v.z; As[kq * 4 + 3][m] = v.w;
        }
        {
            int kk = t >> 4, nq = t & 15;
            float4 v = *(const float4*)&B[(size_t)(kt + kk) * N + n0 + nq * 4];
            *(float4*)&Bs[kk][nq * 4] = v;
        }
        __syncthreads();
#pragma unroll
        for (int kk = 0; kk < 16; kk++) {
            float4 b = *(float4*)&Bs[kk][tx * 4];
            float a[8];
#pragma unroll
            for (int i = 0; i < 8; i++) a[i] = As[kk][ty * 8 + i];
#pragma unroll
            for (int i = 0; i < 8; i++) {
                acc[i][0] += a[i] * b.x; acc[i][1] += a[i] * b.y;
                acc[i][2] += a[i] * b.z; acc[i][3] += a[i] * b.w;
            }
        }
        __syncthreads();
    }
#pragma unroll
    for (int i = 0; i < 8; i++) {
        float4 v = make_float4(acc[i][0], acc[i][1], acc[i][2], acc[i][3]);
        *(float4*)&C[(size_t)(m0 + ty * 8 + i) * N + n0 + tx * 4] = v;
    }
}

// ---------------- split + rmsnorm + pack ----------------
__global__ void pack_norm(const float* __restrict__ qw,
                          const float* __restrict__ k1w,
                          const float* __restrict__ k2w) {
    int blk = blockIdx.x;
    int bh = blk >> 8, n = blk & 255;
    int b = bh >> 3, h = bh & 7;
    int dd = threadIdx.x;
    size_t base = (size_t)(b * 256 + n) * 2560 + h * 64 + dd;
    float q  = g_qkv[base];
    float k1 = g_qkv[base + 512];
    float k2 = g_qkv[base + 1024];
    float v1 = g_qkv[base + 1536];
    float v2 = g_qkv[base + 2048];

    __shared__ float sw[3][2];
    float sq = q * q, s1 = k1 * k1, s2 = k2 * k2;
#pragma unroll
    for (int o = 16; o; o >>= 1) {
        sq += __shfl_xor_sync(0xffffffffu, sq, o);
        s1 += __shfl_xor_sync(0xffffffffu, s1, o);
        s2 += __shfl_xor_sync(0xffffffffu, s2, o);
    }
    int w = dd >> 5;
    if ((dd & 31) == 0) { sw[0][w] = sq; sw[1][w] = s1; sw[2][w] = s2; }
    __syncthreads();
    float rq = rsqrtf((sw[0][0] + sw[0][1]) * (1.f / 64.f) + EPSF);
    float r1 = rsqrtf((sw[1][0] + sw[1][1]) * (1.f / 64.f) + EPSF);
    float r2 = rsqrtf((sw[2][0] + sw[2][1]) * (1.f / 64.f) + EPSF);

    int rb = bh * NS * DH + n * DH + dd;
    g_qn[rb] = q * rq * qw[dd] * 0.125f;
    g_k1[rb] = k1 * r1 * k1w[dd];
    g_k2[rb] = k2 * r2 * k2w[dd];
    g_v1t[bh * DH * NS + dd * NS + n] = v1;
    g_v2t[bh * DH * NS + dd * NS + n] = v2;
}

// ---------------- sims: e = exp(clip(scale * L @ R^T)) ----------------
__global__ void sims_kernel() {
    int z = blockIdx.z;
    int bh = z / 3, mat = z % 3;
    const float* L = ((mat == 2) ? g_k1 : g_qn) + bh * NS * DH;
    const float* R = ((mat == 0) ? g_k1 : g_k2) + bh * NS * DH;
    float* C = ((mat == 0) ? g_e1 : (mat == 1) ? g_e2 : g_e3) + (size_t)bh * NS * NS;
    float scale = (mat == 2) ? 0.125f : 1.f;

    __shared__ float As[16][128];
    __shared__ float Bs[16][64];
    int t = threadIdx.x, tx = t & 15, ty = t >> 4;
    int m0 = blockIdx.y * 128, n0 = blockIdx.x * 64;

    float acc[8][4];
#pragma unroll
    for (int i = 0; i < 8; i++)
#pragma unroll
        for (int j = 0; j < 4; j++) acc[i][j] = 0.f;

    for (int kt = 0; kt < 64; kt += 16) {
#pragma unroll
        for (int q = 0; q < 2; q++) {
            int lin = t + q * 256;
            int m = lin & 127, kq = lin >> 7;
            float4 v = *(const float4*)&L[(m0 + m) * 64 + kt + kq * 4];
            As[kq * 4 + 0][m] = v.x; As[kq * 4 + 1][m] = v.y;
            As[kq * 4 + 2][m] = v.z; As[kq * 4 + 3][m] = v.w;
        }
        {
            int n = t & 63, kq = t >> 6;
            float4 v = *(const float4*)&R[(n0 + n) * 64 + kt + kq * 4];
            Bs[kq * 4 + 0][n] = v.x; Bs[kq * 4 + 1][n] = v.y;
            Bs[kq * 4 + 2][n] = v.z; Bs[kq * 4 + 3][n] = v.w;
        }
        __syncthreads();
#pragma unroll
        for (int kk = 0; kk < 16; kk++) {
            float4 b = *(float4*)&Bs[kk][tx * 4];
            float a[8];
#pragma unroll
            for (int i = 0; i < 8; i++) a[i] = As[kk][ty * 8 + i];
#pragma unroll
            for (int i = 0; i < 8; i++) {
                acc[i][0] += a[i] * b.x; acc[i][1] += a[i] * b.y;
                acc[i][2] += a[i] * b.z; acc[i][3] += a[i] * b.w;
            }
        }
        __syncthreads();
    }
#pragma unroll
    for (int i = 0; i < 8; i++) {
        float4 v;
        v.x = __expf(fminf(40.f, fmaxf(-40.f, acc[i][0] * scale)));
        v.y = __expf(fminf(40.f, fmaxf(-40.f, acc[i][1] * scale)));
        v.z = __expf(fminf(40.f, fmaxf(-40.f, acc[i][2] * scale)));
        v.w = __expf(fminf(40.f, fmaxf(-40.f, acc[i][3] * scale)));
        *(float4*)&C[(size_t)(m0 + ty * 8 + i) * NS + n0 + tx * 4] = v;
    }
}

// ---------------- heavy: mma.sync tf32 factorized attention ----------------
// Per CTA (dg, ih, jh, bh): 13 channels d. For each d:
//   G[i,j] = sum_k (e2[i,k]*v2[k,d]) * e3[j,k]   (64x64x256 via m16n8k8 tf32)
//   partial[i] = sum_j e1[i,j]*v1[j,d]*G[i,j]    (fp32 epilogue on D frags)
// e2 (fp32), e3 (tf32), e1 (fp32) tiles smem-resident across channels.
// Pitch 260 floats (== 4 mod 32) -> conflict-free fragment LDS.
#define PCH 260
#define AS_OFF 0
#define E3_OFF 66560
#define E2_OFF 133120
#define E1_OFF 199680           // pitch 68 floats
#define V2_OFF 217088
#define V1_OFF 218112
#define RED_OFF 218368
#define SMEM_SZ 219392

__global__ void __launch_bounds__(256, 1) heavy_mma() {
    extern __shared__ __align__(16) char smem[];
    float*    Asf = (float*)(smem + AS_OFF);
    uint32_t* Asu = (uint32_t*)(smem + AS_OFF);
    float*    E3f = (float*)(smem + E3_OFF);
    uint32_t* E3u = (uint32_t*)(smem + E3_OFF);
    float*    E2f = (float*)(smem + E2_OFF);
    float*    E1f = (float*)(smem + E1_OFF);
    float*    v2s = (float*)(smem + V2_OFF);
    float*    v1s = (float*)(smem + V1_OFF);
    float*    red = (float*)(smem + RED_OFF);

    int t = threadIdx.x, lane = t & 31, wid = t >> 5;
    int wi = wid >> 2, wj = wid & 3;           // warp grid 2(i) x 4(j)
    int dg = blockIdx.x;                       // 0..4, 13 channels each
    int ih = blockIdx.y >> 2, jh = blockIdx.y & 3;
    int bh = blockIdx.z;

    const float* e2p = g_e2 + (size_t)bh * 65536 + (size_t)(ih * 64) * 256;
    const float* e3p = g_e3 + (size_t)bh * 65536 + (size_t)(jh * 64) * 256;
    const float* e1p = g_e1 + (size_t)bh * 65536 + (size_t)(ih * 64) * 256 + jh * 64;

    // ---- CTA-start loads: e2 (fp32), e3 (tf32), e1 (fp32) ----
    for (int idx = t; idx < 4096; idx += 256) {       // 64 rows x 64 float4
        int r = idx >> 6, q = (idx & 63) << 2;
        float4 a = *(const float4*)&e2p[r * 256 + q];
        *(float4*)&E2f[r * PCH + q] = a;
        float4 b = *(const float4*)&e3p[r * 256 + q];
        uint4 u;
        u.x = cvt_tf32(b.x); u.y = cvt_tf32(b.y);
        u.z = cvt_tf32(b.z); u.w = cvt_tf32(b.w);
        *(uint4*)&E3u[r * PCH + q] = u;
    }
    for (int idx = t; idx < 1024; idx += 256) {       // 64 rows x 16 float4
        int r = idx >> 4, q = (idx & 15) << 2;
        float4 v = *(const float4*)&e1p[r * 256 + q];
        *(float4*)&E1f[r * 68 + q] = v;
    }

    // per-warp fragment base pointers
    const uint32_t* pA = Asu + (wi * 32 + (lane >> 2)) * PCH + (lane & 3);
    const uint32_t* pB = E3u + (wj * 16 + (lane >> 2)) * PCH + (lane & 3);

    // As-build assignment: row = t&63, k-block = (t>>6)*64
    int brow = t & 63, bkb = (t >> 6) << 6;
    const float* e2row = E2f + brow * PCH + bkb;
    uint32_t*    asrow = Asu + brow * PCH + bkb;

    for (int ci = 0; ci < 13; ci++) {
        int d = dg * 13 + ci;
        if (t < 64)  v1s[t] = (d < 64) ? g_v1t[((size_t)bh * DH + d) * NS + jh * 64 + t] : 1.f;
        v2s[t] = (d < 64) ? g_v2t[((size_t)bh * DH + d) * NS + t] : 1.f;
        __syncthreads();

        // build A = tf32(e2 * v2_d)
#pragma unroll
        for (int q = 0; q < 16; q++) {
            float4 a = *(const float4*)(e2row + q * 4);
            float4 w = *(const float4*)&v2s[bkb + q * 4];
            uint4 u;
            u.x = cvt_tf32(a.x * w.x); u.y = cvt_tf32(a.y * w.y);
            u.z = cvt_tf32(a.z * w.z); u.w = cvt_tf32(a.w * w.w);
            *(uint4*)(asrow + q * 4) = u;
        }
        __syncthreads();

        // ---- MMA mainloop: 32 k-steps of 8 ----
        float acc[2][2][4];
#pragma unroll
        for (int m = 0; m < 2; m++)
#pragma unroll
            for (int n = 0; n < 2; n++)
#pragma unroll
                for (int c = 0; c < 4; c++) acc[m][n][c] = 0.f;

#pragma unroll 4
        for (int ks = 0; ks < 32; ks++) {
            int k0 = ks * 8;
            uint32_t a0[2], a1[2], a2[2], a3[2], b0[2], b1[2];
#pragma unroll
            for (int mt = 0; mt < 2; mt++) {
                const uint32_t* p = pA + mt * 16 * PCH + k0;
                a0[mt] = p[0]; a1[mt] = p[8 * PCH];
                a2[mt] = p[4]; a3[mt] = p[8 * PCH + 4];
            }
#pragma unroll
            for (int nt = 0; nt < 2; nt++) {
                const uint32_t* p = pB + nt * 8 * PCH + k0;
                b0[nt] = p[0]; b1[nt] = p[4];
            }
#pragma unroll
            for (int mt = 0; mt < 2; mt++)
#pragma unroll
                for (int nt = 0; nt < 2; nt++)
                    mma_tf32(acc[mt][nt], a0[mt], a1[mt], a2[mt], a3[mt], b0[nt], b1[nt]);
        }

        // ---- epilogue: sum_j e1[i,j]*v1[j]*G[i,j] ----
#pragma unroll
        for (int mt = 0; mt < 2; mt++) {
            float p0 = 0.f, p1 = 0.f;
            int i0 = wi * 32 + mt * 16 + (lane >> 2);
#pragma unroll
            for (int nt = 0; nt < 2; nt++) {
                int j = wj * 16 + nt * 8 + (lane & 3) * 2;
                float vj0 = v1s[j], vj1 = v1s[j + 1];
                float w0 = E1f[i0 * 68 + j] * vj0;
                float w1 = E1f[i0 * 68 + j + 1] * vj1;
                float w2 = E1f[(i0 + 8) * 68 + j] * vj0;
                float w3 = E1f[(i0 + 8) * 68 + j + 1] * vj1;
                p0 += acc[mt][nt][0] * w0 + acc[mt][nt][1] * w1;
                p1 += acc[mt][nt][2] * w2 + acc[mt][nt][3] * w3;
            }
            p0 += __shfl_xor_sync(0xffffffffu, p0, 1);
            p0 += __shfl_xor_sync(0xffffffffu, p0, 2);
            p1 += __shfl_xor_sync(0xffffffffu, p1, 1);
            p1 += __shfl_xor_sync(0xffffffffu, p1, 2);
            if ((lane & 3) == 0) {
                red[(i0) * 4 + wj] = p0;
                red[(i0 + 8) * 4 + wj] = p1;
            }
        }
        __syncthreads();
        if (t < 64) {
            float s = red[t * 4] + red[t * 4 + 1] + red[t * 4 + 2] + red[t * 4 + 3];
            int ig = ih * 64 + t;
            if (d < 64) g_numP[jh][((size_t)bh * NS + ig) * DH + d] = s;
            else        g_denP[jh][(size_t)bh * NS + ig] = s;
        }
        __syncthreads();
    }
}

// ---------------- normalize: combine 4 jh partials, o = num/den ----------------
__global__ void normalize_kernel() {
    int idx = blockIdx.x * 256 + threadIdx.x;   // 0..262143
    int dd = idx & 63;
    int i  = (idx >> 6) & 255;
    int bh = idx >> 14;
    int b = bh >> 3, h = bh & 7;
    float num = g_numP[0][idx] + g_numP[1][idx] + g_numP[2][idx] + g_numP[3][idx];
    float den = g_denP[0][bh * NS + i] + g_denP[1][bh * NS + i]
              + g_denP[2][bh * NS + i] + g_denP[3][bh * NS + i];
    g_o[(size_t)(b * 256 + i) * 512 + h * 64 + dd] = num / den;
}

extern "C" void kernel_launch(void* const* d_in, const int* in_sizes, int n_in,
                              void* d_out, int out_size) {
    const float* x     = (const float*)d_in[0];
    const float* w_qkv = (const float*)d_in[1];
    const float* w_out = (const float*)d_in[2];
    const float* qw    = (const float*)d_in[3];
    const float* k1w   = (const float*)d_in[4];
    const float* k2w   = (const float*)d_in[5];
    float* out = (float*)d_out;

    float *qkv_p = nullptr, *o_p = nullptr;
    cudaGetSymbolAddress((void**)&qkv_p, g_qkv);
    cudaGetSymbolAddress((void**)&o_p, g_o);

    cudaFuncSetAttribute(heavy_mma, cudaFuncAttributeMaxDynamicSharedMemorySize, SMEM_SZ);

    // 1) qkv = x @ w_qkv   [512,512]@[512,2560]
    sgemm128x64<<<dim3(40, 4), 256>>>(x, w_qkv, qkv_p, 512, 2560, 512);
    // 2) split + rmsnorm + pack
    pack_norm<<<4096, 64>>>(qw, k1w, k2w);
    // 3) e1/e2/e3
    sims_kernel<<<dim3(4, 2, 48), 256>>>();
    // 4) heavy factorized attention (mma.sync tf32): 5 dgroups x (ih,jh) x bh
    heavy_mma<<<dim3(5, 16, 16), 256, SMEM_SZ>>>();
    // 5) normalize (sum 4 jh partials)
    normalize_kernel<<<1024, 256>>>();
    // 6) out = o @ w_out   [512,512]@[512,512]
    sgemm128x64<<<dim3(8, 4), 256>>>(o_p, w_out, out, 512, 512, 512);
}